// round 14
// baseline (speedup 1.0000x reference)
#include <cuda_runtime.h>
#include <cuda_fp16.h>
#include <cstdint>

#define NN 50000
#define NE 800000
#define NF 512
#define NH 128
#define NC 40
#define CAP 96    // max edges per node bucket (Poisson(16): P(deg>=96) < 1e-30)

// ---------------- scratch (device globals; no allocation allowed) ----------------
__device__ __half g_s1h[(size_t)NN * NH];   // x @ W1 (fp16)
__device__ __half g_h  [(size_t)NN * NH];   // relu(agg1+b1) (fp16)
__device__ __half g_s2h[(size_t)NN * NC];   // h @ W2 (fp16)
__device__ int    g_cursor[NN];
__device__ int2   g_edge[(size_t)NN * CAP]; // bucketed (src, weight-bits)
__device__ __half g_w1t[(size_t)NH * NF];   // W1^T fp16: [n][k]
__device__ __half g_w2t_hi[(size_t)NC * NH];
__device__ __half g_w2t_lo[(size_t)NC * NH];

// ---------------- PTX helpers (portable: sm_80-level only) ----------------
__device__ __forceinline__ uint32_t smem_u32(const void* p) {
    uint32_t a;
    asm("{ .reg .u64 t; cvta.to.shared.u64 t, %1; cvt.u32.u64 %0, t; }"
        : "=r"(a) : "l"(p));
    return a;
}
__device__ __forceinline__ void ldsm_x4(uint32_t* r, uint32_t addr) {
    asm volatile("ldmatrix.sync.aligned.m8n8.x4.shared.b16 {%0,%1,%2,%3}, [%4];"
                 : "=r"(r[0]), "=r"(r[1]), "=r"(r[2]), "=r"(r[3]) : "r"(addr));
}
__device__ __forceinline__ void ldsm_x2(uint32_t* r, uint32_t addr) {
    asm volatile("ldmatrix.sync.aligned.m8n8.x2.shared.b16 {%0,%1}, [%2];"
                 : "=r"(r[0]), "=r"(r[1]) : "r"(addr));
}
__device__ __forceinline__ void mma_f16(float* c, const uint32_t* a, const uint32_t* b) {
    asm volatile(
        "mma.sync.aligned.m16n8k16.row.col.f32.f16.f16.f32 "
        "{%0,%1,%2,%3}, {%4,%5,%6,%7}, {%8,%9}, {%0,%1,%2,%3};"
        : "+f"(c[0]), "+f"(c[1]), "+f"(c[2]), "+f"(c[3])
        : "r"(a[0]), "r"(a[1]), "r"(a[2]), "r"(a[3]), "r"(b[0]), "r"(b[1]));
}
__device__ __forceinline__ void cp_async16(uint32_t dst, const void* src, int srcbytes) {
    asm volatile("cp.async.cg.shared.global [%0], [%1], 16, %2;"
                 :: "r"(dst), "l"(src), "r"(srcbytes));
}
#define CP_COMMIT() asm volatile("cp.async.commit_group;" ::: "memory")
#define CP_WAIT0()  asm volatile("cp.async.wait_group 0;" ::: "memory")

// ---------------- bucketed edge fill (no prefix-sum needed) ----------------
__global__ void k_fill4(const int4* __restrict__ src4, const int4* __restrict__ dst4,
                        const float4* __restrict__ w4) {
    int i = blockIdx.x * blockDim.x + threadIdx.x;
    if (i < NE / 4) {
        int4 s = src4[i];
        int4 d = dst4[i];
        float4 w = w4[i];
        int c0 = atomicAdd(&g_cursor[d.x], 1);
        if (c0 < CAP) g_edge[(size_t)d.x * CAP + c0] = make_int2(s.x, __float_as_int(w.x));
        int c1 = atomicAdd(&g_cursor[d.y], 1);
        if (c1 < CAP) g_edge[(size_t)d.y * CAP + c1] = make_int2(s.y, __float_as_int(w.y));
        int c2 = atomicAdd(&g_cursor[d.z], 1);
        if (c2 < CAP) g_edge[(size_t)d.z * CAP + c2] = make_int2(s.z, __float_as_int(w.z));
        int c3 = atomicAdd(&g_cursor[d.w], 1);
        if (c3 < CAP) g_edge[(size_t)d.w * CAP + c3] = make_int2(s.w, __float_as_int(w.w));
    }
}

// ---------------- fused weight transpose / split (one launch) ----------------
__global__ void k_wsplit(const float* __restrict__ W1, const float* __restrict__ W2) {
    int idx = blockIdx.x * blockDim.x + threadIdx.x;
    if (idx < NF * NH) {
        int k = idx >> 7;
        int n = idx & 127;
        g_w1t[(size_t)n * NF + k] = __float2half_rn(W1[idx]);
    } else {
        int j = idx - NF * NH;
        if (j < NH * NC) {
            int k = j / NC;
            int n = j % NC;
            float v = W2[j];
            __half hi = __float2half_rn(v);
            __half lo = __float2half_rn(v - __half2float(hi));
            g_w2t_hi[(size_t)n * NH + k] = hi;
            g_w2t_lo[(size_t)n * NH + k] = lo;
        }
    }
}

// ---------------- GEMM1: M=64 tiles, direct-LDG A path, cp.async B -------------
#define BM      64
#define BK      64
#define NCHUNK  (NF / BK)          // 8
#define LDA     72                 // fp16 per smem row (144 B)
#define APLN    (BM * LDA * 2)     // 9216 B
#define BPLN    (128 * LDA * 2)    // 18432 B
#define SA      0
#define SB0     APLN
#define SB1     (APLN + BPLN)
#define SMEM_SZ (APLN + 2 * BPLN)  // 46080 B

__global__ __launch_bounds__(256, 3) void k_gemm1_mma(const float* __restrict__ x,
                                                      __half* __restrict__ s1) {
    extern __shared__ __align__(16) char smem[];
    const uint32_t sb = smem_u32(smem);
    const int tid = threadIdx.x;
    const int lane = tid & 31;
    const int wid = tid >> 5;
    const int wm = wid >> 2;          // 0..1  (32 rows each)
    const int wn = wid & 3;           // 0..3  (32 cols each)
    const int m0 = blockIdx.x * BM;
    const __half* __restrict__ Bw = g_w1t;

    float acc[2][4][4];
#pragma unroll
    for (int i = 0; i < 2; i++)
#pragma unroll
        for (int j = 0; j < 4; j++)
#pragma unroll
            for (int q = 0; q < 4; q++) acc[i][j][q] = 0.f;

    const uint32_t a_base = sb + SA +
        (uint32_t)(wm * 32 + (lane & 15)) * (LDA * 2) + (uint32_t)((lane >> 4) * 16);
    const uint32_t b_base0 = sb + SB0 +
        (uint32_t)(wn * 32 + (lane & 7)) * (LDA * 2) + (uint32_t)(((lane >> 3) & 1) * 16);

    // per-thread A addresses: 4 float4 per chunk (r = idx>>4 in 0..63, g = idx&15)
    const int ar[4] = { tid >> 4, (256 + tid) >> 4, (512 + tid) >> 4, (768 + tid) >> 4 };
    const int ag = tid & 15;

#define ISSUE_B(c, buf)                                                       \
    {                                                                         \
        _Pragma("unroll")                                                     \
        for (int it = 0; it < 4; it++) {                                      \
            int idx = it * 256 + tid;                                         \
            int n = idx >> 3, g = idx & 7;                                    \
            const __half* src = Bw + (size_t)n * NF + (c) * BK + g * 8;       \
            cp_async16(sb + (buf) + (uint32_t)(n * (LDA * 2) + g * 16), src, 16); \
        }                                                                     \
    }

    ISSUE_B(0, SB0);
    CP_COMMIT();

#pragma unroll
    for (int c = 0; c < NCHUNK; c++) {
        // batch-issue direct A loads (overlap previous compute tail + sync)
        float4 va[4];
#pragma unroll
        for (int it = 0; it < 4; it++) {
            int row = m0 + ar[it];
            va[it] = make_float4(0.f, 0.f, 0.f, 0.f);
            if (row < NN)
                va[it] = *(const float4*)(x + (size_t)row * NF + c * BK + ag * 4);
        }
        if (c > 0) __syncthreads();   // previous compute done with SA
        // convert in registers -> fp16 A plane
#pragma unroll
        for (int it = 0; it < 4; it++) {
            __half2 ha = __floats2half2_rn(va[it].x, va[it].y);
            __half2 hb = __floats2half2_rn(va[it].z, va[it].w);
            uint32_t off = (uint32_t)(ar[it] * (LDA * 2) + ag * 8);
            asm volatile("st.shared.v2.b32 [%0], {%1, %2};"
                         :: "r"(sb + SA + off),
                            "r"(*(uint32_t*)&ha), "r"(*(uint32_t*)&hb));
        }
        CP_WAIT0();                   // B(c) arrived
        __syncthreads();              // SA + SB[c&1] visible to all
        if (c < NCHUNK - 1) {
            ISSUE_B(c + 1, ((c + 1) & 1) ? SB1 : SB0);
            CP_COMMIT();
        }
        const uint32_t bb_base = b_base0 + (uint32_t)((c & 1) ? (SB1 - SB0) : 0);
#pragma unroll
        for (int ks = 0; ks < 4; ks++) {
            uint32_t ah[2][4];
#pragma unroll
            for (int mi = 0; mi < 2; mi++) {
                uint32_t aa = a_base + (uint32_t)(mi * 16 * (LDA * 2) + ks * 32);
                ldsm_x4(ah[mi], aa);
            }
#pragma unroll
            for (int ni = 0; ni < 4; ni++) {
                uint32_t ba = bb_base + (uint32_t)(ni * 8 * (LDA * 2) + ks * 32);
                uint32_t bb[2];
                ldsm_x2(bb, ba);
#pragma unroll
                for (int mi = 0; mi < 2; mi++)
                    mma_f16(acc[mi][ni], ah[mi], bb);
            }
        }
    }

    const int rbase = m0 + wm * 32 + (lane >> 2);
    const int cbase = wn * 32 + 2 * (lane & 3);
#pragma unroll
    for (int mi = 0; mi < 2; mi++) {
        int r0 = rbase + mi * 16;
        int r1 = r0 + 8;
#pragma unroll
        for (int ni = 0; ni < 4; ni++) {
            int col = cbase + ni * 8;
            if (r0 < NN)
                *(__half2*)(s1 + (size_t)r0 * NH + col) =
                    __floats2half2_rn(acc[mi][ni][0], acc[mi][ni][1]);
            if (r1 < NN)
                *(__half2*)(s1 + (size_t)r1 * NH + col) =
                    __floats2half2_rn(acc[mi][ni][2], acc[mi][ni][3]);
        }
    }
}

// ---------------- agg layer 1: fp16 gather + bias + relu -> fp16 h -------------
__global__ void k_agg1(const float* __restrict__ bias) {
    int idx = blockIdx.x * blockDim.x + threadIdx.x;
    int n = idx >> 5;
    int f = idx & 31;
    if (n >= NN) return;
    int cnt = g_cursor[n];
    if (cnt > CAP) cnt = CAP;
    int beg = n * CAP, end = beg + cnt;
    const uint2* s2v = (const uint2*)g_s1h;
    float4 acc = make_float4(0.f, 0.f, 0.f, 0.f);
    int e = beg;
    for (; e + 1 < end; e += 2) {
        int2 e0 = g_edge[e], e1 = g_edge[e + 1];
        float w0 = __int_as_float(e0.y), w1 = __int_as_float(e1.y);
        uint2 u0 = s2v[(size_t)e0.x * 32 + f];
        uint2 u1 = s2v[(size_t)e1.x * 32 + f];
        float2 a0 = __half22float2(*(__half2*)&u0.x);
        float2 b0 = __half22float2(*(__half2*)&u0.y);
        float2 a1 = __half22float2(*(__half2*)&u1.x);
        float2 b1 = __half22float2(*(__half2*)&u1.y);
        acc.x = fmaf(a0.x, w0, acc.x); acc.y = fmaf(a0.y, w0, acc.y);
        acc.z = fmaf(b0.x, w0, acc.z); acc.w = fmaf(b0.y, w0, acc.w);
        acc.x = fmaf(a1.x, w1, acc.x); acc.y = fmaf(a1.y, w1, acc.y);
        acc.z = fmaf(b1.x, w1, acc.z); acc.w = fmaf(b1.y, w1, acc.w);
    }
    if (e < end) {
        int2 e0 = g_edge[e];
        float w = __int_as_float(e0.y);
        uint2 u = s2v[(size_t)e0.x * 32 + f];
        float2 a = __half22float2(*(__half2*)&u.x);
        float2 b = __half22float2(*(__half2*)&u.y);
        acc.x = fmaf(a.x, w, acc.x); acc.y = fmaf(a.y, w, acc.y);
        acc.z = fmaf(b.x, w, acc.z); acc.w = fmaf(b.y, w, acc.w);
    }
    float4 b = ((const float4*)bias)[f];
    acc.x = fmaxf(acc.x + b.x, 0.f);
    acc.y = fmaxf(acc.y + b.y, 0.f);
    acc.z = fmaxf(acc.z + b.z, 0.f);
    acc.w = fmaxf(acc.w + b.w, 0.f);
    __half2 h01 = __floats2half2_rn(acc.x, acc.y);
    __half2 h23 = __floats2half2_rn(acc.z, acc.w);
    uint2 hv = make_uint2(*(uint32_t*)&h01, *(uint32_t*)&h23);
    *(uint2*)(g_h + (size_t)n * NH + f * 4) = hv;
}

// ---------------- agg layer 2: fp16 gather + bias -> fp32 out ----------------
__global__ void k_agg2(const float* __restrict__ bias, float* __restrict__ out) {
    int idx = blockIdx.x * blockDim.x + threadIdx.x;
    int n = idx / 10;
    int f = idx % 10;
    if (n >= NN) return;
    int cnt = g_cursor[n];
    if (cnt > CAP) cnt = CAP;
    int beg = n * CAP, end = beg + cnt;
    const uint2* s2v = (const uint2*)g_s2h;
    float4 acc = make_float4(0.f, 0.f, 0.f, 0.f);
    int e = beg;
    for (; e + 1 < end; e += 2) {
        int2 e0 = g_edge[e], e1 = g_edge[e + 1];
        float w0 = __int_as_float(e0.y), w1 = __int_as_float(e1.y);
        uint2 u0 = s2v[(size_t)e0.x * 10 + f];
        uint2 u1 = s2v[(size_t)e1.x * 10 + f];
        float2 a0 = __half22float2(*(__half2*)&u0.x);
        float2 b0 = __half22float2(*(__half2*)&u0.y);
        float2 a1 = __half22float2(*(__half2*)&u1.x);
        float2 b1 = __half22float2(*(__half2*)&u1.y);
        acc.x = fmaf(a0.x, w0, acc.x); acc.y = fmaf(a0.y, w0, acc.y);
        acc.z = fmaf(b0.x, w0, acc.z); acc.w = fmaf(b0.y, w0, acc.w);
        acc.x = fmaf(a1.x, w1, acc.x); acc.y = fmaf(a1.y, w1, acc.y);
        acc.z = fmaf(b1.x, w1, acc.z); acc.w = fmaf(b1.y, w1, acc.w);
    }
    if (e < end) {
        int2 e0 = g_edge[e];
        float w = __int_as_float(e0.y);
        uint2 u = s2v[(size_t)e0.x * 10 + f];
        float2 a = __half22float2(*(__half2*)&u.x);
        float2 b = __half22float2(*(__half2*)&u.y);
        acc.x = fmaf(a.x, w, acc.x); acc.y = fmaf(a.y, w, acc.y);
        acc.z = fmaf(b.x, w, acc.z); acc.w = fmaf(b.y, w, acc.w);
    }
    float4 b = ((const float4*)bias)[f];
    acc.x += b.x; acc.y += b.y; acc.z += b.z; acc.w += b.w;
    ((float4*)out)[(size_t)n * 10 + f] = acc;
}

// ---------------- GEMM2: s2h = h @ W2 (A fp16, B split fp16 hi/lo; 2 MMA) ------
#define LDA2    136                        // fp16 per smem row (272 B)
#define APL     (128 * LDA2 * 2)           // 34816 B
#define BPL     (40 * LDA2 * 2)            // 10880 B
#define S2A     0
#define S2B_HI  APL
#define S2B_LO  (APL + BPL)
#define SMEM2_SZ (APL + 2 * BPL)           // 56576 B

__global__ __launch_bounds__(256) void k_gemm2_mma(__half* __restrict__ s2) {
    extern __shared__ __align__(16) char smem[];
    const uint32_t sb = smem_u32(smem);
    const int tid = threadIdx.x;
    const int lane = tid & 31;
    const int wid = tid >> 5;
    const int n0 = blockIdx.x * 128;

#pragma unroll
    for (int it = 0; it < 8; it++) {
        int idx = it * 256 + tid;
        int r = idx >> 4, g = idx & 15;
        int row = n0 + r;
        uint4 vh = make_uint4(0, 0, 0, 0);
        if (row < NN)
            vh = *(const uint4*)(g_h + (size_t)row * NH + g * 8);
        uint32_t off = (uint32_t)(r * (LDA2 * 2) + g * 16);
        asm volatile("st.shared.v4.b32 [%0], {%1,%2,%3,%4};"
                     :: "r"(sb + S2A + off), "r"(vh.x), "r"(vh.y), "r"(vh.z), "r"(vh.w));
    }
#pragma unroll
    for (int it = 0; it < 3; it++) {
        int idx = it * 256 + tid;
        if (idx < 640) {
            int r = idx >> 4, g = idx & 15;
            uint4 vh = *(const uint4*)(g_w2t_hi + (size_t)r * NH + g * 8);
            uint4 vl = *(const uint4*)(g_w2t_lo + (size_t)r * NH + g * 8);
            uint32_t off = (uint32_t)(r * (LDA2 * 2) + g * 16);
            asm volatile("st.shared.v4.b32 [%0], {%1,%2,%3,%4};"
                         :: "r"(sb + S2B_HI + off), "r"(vh.x), "r"(vh.y), "r"(vh.z), "r"(vh.w));
            asm volatile("st.shared.v4.b32 [%0], {%1,%2,%3,%4};"
                         :: "r"(sb + S2B_LO + off), "r"(vl.x), "r"(vl.y), "r"(vl.z), "r"(vl.w));
        }
    }
    __syncthreads();

    float acc[5][4];
#pragma unroll
    for (int i = 0; i < 5; i++)
#pragma unroll
        for (int q = 0; q < 4; q++) acc[i][q] = 0.f;

    const uint32_t a_base = sb + S2A +
        (uint32_t)(wid * 16 + (lane & 15)) * (LDA2 * 2) + (uint32_t)((lane >> 4) * 16);
    const uint32_t b_base = sb + S2B_HI +
        (uint32_t)(lane & 7) * (LDA2 * 2) + (uint32_t)(((lane >> 3) & 1) * 16);

#pragma unroll
    for (int ks = 0; ks < 8; ks++) {
        uint32_t ah[4];
        ldsm_x4(ah, a_base + (uint32_t)(ks * 32));
#pragma unroll
        for (int nt = 0; nt < 5; nt++) {
            uint32_t ba = b_base + (uint32_t)(nt * 8 * (LDA2 * 2) + ks * 32);
            uint32_t bh[2], bl[2];
            ldsm_x2(bh, ba);
            ldsm_x2(bl, ba + (uint32_t)(S2B_LO - S2B_HI));
            mma_f16(acc[nt], ah, bh);
            mma_f16(acc[nt], ah, bl);
        }
    }

    const int r0 = n0 + wid * 16 + (lane >> 2);
    const int r1 = r0 + 8;
    const int cb = 2 * (lane & 3);
#pragma unroll
    for (int nt = 0; nt < 5; nt++) {
        int col = cb + nt * 8;
        if (r0 < NN)
            *(__half2*)(s2 + (size_t)r0 * NC + col) =
                __floats2half2_rn(acc[nt][0], acc[nt][1]);
        if (r1 < NN)
            *(__half2*)(s2 + (size_t)r1 * NC + col) =
                __floats2half2_rn(acc[nt][2], acc[nt][3]);
    }
}

// ---------------- launcher with capture fork/join ----------------
extern "C" void kernel_launch(void* const* d_in, const int* in_sizes, int n_in,
                              void* d_out, int out_size) {
    const float* x  = (const float*)d_in[0];
    const int*   es = (const int*)d_in[1];
    const int*   ed = (const int*)d_in[2];
    const float* ew = (const float*)d_in[3];
    const float* W1 = (const float*)d_in[4];
    const float* b1 = (const float*)d_in[5];
    const float* W2 = (const float*)d_in[6];
    const float* b2 = (const float*)d_in[7];
    float* out = (float*)d_out;

    __half *s1p, *s2p;
    int *curp;
    cudaGetSymbolAddress((void**)&s1p, g_s1h);
    cudaGetSymbolAddress((void**)&s2p, g_s2h);
    cudaGetSymbolAddress((void**)&curp, g_cursor);

    cudaFuncSetAttribute(k_gemm1_mma, cudaFuncAttributeMaxDynamicSharedMemorySize, SMEM_SZ);
    cudaFuncSetAttribute(k_gemm2_mma, cudaFuncAttributeMaxDynamicSharedMemorySize, SMEM2_SZ);

    static cudaStream_t s2s = nullptr;
    static cudaEvent_t eFork = nullptr, eCSR = nullptr;
    if (!s2s) {
        cudaStreamCreateWithFlags(&s2s, cudaStreamNonBlocking);
        cudaEventCreateWithFlags(&eFork, cudaEventDisableTiming);
        cudaEventCreateWithFlags(&eCSR, cudaEventDisableTiming);
    }

    // fork: bucketed edge fill on side stream
    cudaEventRecord(eFork, 0);
    cudaStreamWaitEvent(s2s, eFork, 0);
    cudaMemsetAsync(curp, 0, NN * sizeof(int), s2s);
    k_fill4<<<(NE / 4 + 255) / 256, 256, 0, s2s>>>((const int4*)es, (const int4*)ed,
                                                   (const float4*)ew);
    cudaEventRecord(eCSR, s2s);

    // main stream: fused weight prep + GEMM1 (independent of edges)
    k_wsplit<<<(NF * NH + NH * NC + 255) / 256, 256>>>(W1, W2);
    k_gemm1_mma<<<(NN + BM - 1) / BM, 256, SMEM_SZ>>>(x, s1p);

    // join, then the dependent tail
    cudaStreamWaitEvent(0, eCSR, 0);
    k_agg1<<<(NN * 32 + 255) / 256, 256>>>(b1);
    k_gemm2_mma<<<(NN + 127) / 128, 256, SMEM2_SZ>>>(s2p);
    k_agg2<<<(NN * 10 + 255) / 256, 256>>>(b2, out);
}

// round 15
// speedup vs baseline: 1.0686x; 1.0686x over previous
#include <cuda_runtime.h>
#include <cuda_fp16.h>
#include <cstdint>

#define NN 50000
#define NE 800000
#define NF 512
#define NH 128
#define NC 40
#define CAP 96    // max edges per node bucket (Poisson(16): P(deg>=96) < 1e-30)

// ---------------- scratch (device globals; no allocation allowed) ----------------
__device__ __half g_s1h[(size_t)NN * NH];   // x @ W1 (fp16)
__device__ __half g_h  [(size_t)NN * NH];   // relu(agg1+b1) (fp16)
__device__ __half g_s2h[(size_t)NN * NC];   // h @ W2 (fp16)
__device__ int    g_cursor[NN];
__device__ int2   g_edge[(size_t)NN * CAP]; // bucketed (src, weight-bits)
__device__ __half g_w1t[(size_t)NH * NF];   // W1^T fp16: [n][k]
__device__ __half g_w2t_hi[(size_t)NC * NH];
__device__ __half g_w2t_lo[(size_t)NC * NH];

// ---------------- PTX helpers (portable: sm_80-level only) ----------------
__device__ __forceinline__ uint32_t smem_u32(const void* p) {
    uint32_t a;
    asm("{ .reg .u64 t; cvta.to.shared.u64 t, %1; cvt.u32.u64 %0, t; }"
        : "=r"(a) : "l"(p));
    return a;
}
__device__ __forceinline__ void ldsm_x4(uint32_t* r, uint32_t addr) {
    asm volatile("ldmatrix.sync.aligned.m8n8.x4.shared.b16 {%0,%1,%2,%3}, [%4];"
                 : "=r"(r[0]), "=r"(r[1]), "=r"(r[2]), "=r"(r[3]) : "r"(addr));
}
__device__ __forceinline__ void ldsm_x2(uint32_t* r, uint32_t addr) {
    asm volatile("ldmatrix.sync.aligned.m8n8.x2.shared.b16 {%0,%1}, [%2];"
                 : "=r"(r[0]), "=r"(r[1]) : "r"(addr));
}
__device__ __forceinline__ void mma_f16(float* c, const uint32_t* a, const uint32_t* b) {
    asm volatile(
        "mma.sync.aligned.m16n8k16.row.col.f32.f16.f16.f32 "
        "{%0,%1,%2,%3}, {%4,%5,%6,%7}, {%8,%9}, {%0,%1,%2,%3};"
        : "+f"(c[0]), "+f"(c[1]), "+f"(c[2]), "+f"(c[3])
        : "r"(a[0]), "r"(a[1]), "r"(a[2]), "r"(a[3]), "r"(b[0]), "r"(b[1]));
}
__device__ __forceinline__ void cp_async16(uint32_t dst, const void* src, int srcbytes) {
    asm volatile("cp.async.cg.shared.global [%0], [%1], 16, %2;"
                 :: "r"(dst), "l"(src), "r"(srcbytes));
}
#define CP_COMMIT() asm volatile("cp.async.commit_group;" ::: "memory")
#define CP_WAIT0()  asm volatile("cp.async.wait_group 0;" ::: "memory")

// ---------------- bucketed edge fill (no prefix-sum needed) ----------------
__global__ void k_fill4(const int4* __restrict__ src4, const int4* __restrict__ dst4,
                        const float4* __restrict__ w4) {
    int i = blockIdx.x * blockDim.x + threadIdx.x;
    if (i < NE / 4) {
        int4 s = src4[i];
        int4 d = dst4[i];
        float4 w = w4[i];
        int c0 = atomicAdd(&g_cursor[d.x], 1);
        if (c0 < CAP) g_edge[(size_t)d.x * CAP + c0] = make_int2(s.x, __float_as_int(w.x));
        int c1 = atomicAdd(&g_cursor[d.y], 1);
        if (c1 < CAP) g_edge[(size_t)d.y * CAP + c1] = make_int2(s.y, __float_as_int(w.y));
        int c2 = atomicAdd(&g_cursor[d.z], 1);
        if (c2 < CAP) g_edge[(size_t)d.z * CAP + c2] = make_int2(s.z, __float_as_int(w.z));
        int c3 = atomicAdd(&g_cursor[d.w], 1);
        if (c3 < CAP) g_edge[(size_t)d.w * CAP + c3] = make_int2(s.w, __float_as_int(w.w));
    }
}

// ---------------- fused weight transpose / split (one launch) ----------------
__global__ void k_wsplit(const float* __restrict__ W1, const float* __restrict__ W2) {
    int idx = blockIdx.x * blockDim.x + threadIdx.x;
    if (idx < NF * NH) {
        int k = idx >> 7;
        int n = idx & 127;
        g_w1t[(size_t)n * NF + k] = __float2half_rn(W1[idx]);
    } else {
        int j = idx - NF * NH;
        if (j < NH * NC) {
            int k = j / NC;
            int n = j % NC;
            float v = W2[j];
            __half hi = __float2half_rn(v);
            __half lo = __float2half_rn(v - __half2float(hi));
            g_w2t_hi[(size_t)n * NH + k] = hi;
            g_w2t_lo[(size_t)n * NH + k] = lo;
        }
    }
}

// ---------------- GEMM1: M=64 tiles, direct-LDG A path, cp.async B -------------
#define BM      64
#define BK      64
#define NCHUNK  (NF / BK)          // 8
#define LDA     72                 // fp16 per smem row (144 B)
#define APLN    (BM * LDA * 2)     // 9216 B
#define BPLN    (128 * LDA * 2)    // 18432 B
#define SA      0
#define SB0     APLN
#define SB1     (APLN + BPLN)
#define SMEM_SZ (APLN + 2 * BPLN)  // 46080 B

__global__ __launch_bounds__(256, 3) void k_gemm1_mma(const float* __restrict__ x,
                                                      __half* __restrict__ s1) {
    extern __shared__ __align__(16) char smem[];
    const uint32_t sb = smem_u32(smem);
    const int tid = threadIdx.x;
    const int lane = tid & 31;
    const int wid = tid >> 5;
    const int wm = wid >> 2;
    const int wn = wid & 3;
    const int m0 = blockIdx.x * BM;
    const __half* __restrict__ Bw = g_w1t;

    float acc[2][4][4];
#pragma unroll
    for (int i = 0; i < 2; i++)
#pragma unroll
        for (int j = 0; j < 4; j++)
#pragma unroll
            for (int q = 0; q < 4; q++) acc[i][j][q] = 0.f;

    const uint32_t a_base = sb + SA +
        (uint32_t)(wm * 32 + (lane & 15)) * (LDA * 2) + (uint32_t)((lane >> 4) * 16);
    const uint32_t b_base0 = sb + SB0 +
        (uint32_t)(wn * 32 + (lane & 7)) * (LDA * 2) + (uint32_t)(((lane >> 3) & 1) * 16);

    const int ar[4] = { tid >> 4, (256 + tid) >> 4, (512 + tid) >> 4, (768 + tid) >> 4 };
    const int ag = tid & 15;

#define ISSUE_B(c, buf)                                                       \
    {                                                                         \
        _Pragma("unroll")                                                     \
        for (int it = 0; it < 4; it++) {                                      \
            int idx = it * 256 + tid;                                         \
            int n = idx >> 3, g = idx & 7;                                    \
            const __half* src = Bw + (size_t)n * NF + (c) * BK + g * 8;       \
            cp_async16(sb + (buf) + (uint32_t)(n * (LDA * 2) + g * 16), src, 16); \
        }                                                                     \
    }

    ISSUE_B(0, SB0);
    CP_COMMIT();

#pragma unroll
    for (int c = 0; c < NCHUNK; c++) {
        float4 va[4];
#pragma unroll
        for (int it = 0; it < 4; it++) {
            int row = m0 + ar[it];
            va[it] = make_float4(0.f, 0.f, 0.f, 0.f);
            if (row < NN)
                va[it] = *(const float4*)(x + (size_t)row * NF + c * BK + ag * 4);
        }
        if (c > 0) __syncthreads();
#pragma unroll
        for (int it = 0; it < 4; it++) {
            __half2 ha = __floats2half2_rn(va[it].x, va[it].y);
            __half2 hb = __floats2half2_rn(va[it].z, va[it].w);
            uint32_t off = (uint32_t)(ar[it] * (LDA * 2) + ag * 8);
            asm volatile("st.shared.v2.b32 [%0], {%1, %2};"
                         :: "r"(sb + SA + off),
                            "r"(*(uint32_t*)&ha), "r"(*(uint32_t*)&hb));
        }
        CP_WAIT0();
        __syncthreads();
        if (c < NCHUNK - 1) {
            ISSUE_B(c + 1, ((c + 1) & 1) ? SB1 : SB0);
            CP_COMMIT();
        }
        const uint32_t bb_base = b_base0 + (uint32_t)((c & 1) ? (SB1 - SB0) : 0);
#pragma unroll
        for (int ks = 0; ks < 4; ks++) {
            uint32_t ah[2][4];
#pragma unroll
            for (int mi = 0; mi < 2; mi++) {
                uint32_t aa = a_base + (uint32_t)(mi * 16 * (LDA * 2) + ks * 32);
                ldsm_x4(ah[mi], aa);
            }
#pragma unroll
            for (int ni = 0; ni < 4; ni++) {
                uint32_t ba = bb_base + (uint32_t)(ni * 8 * (LDA * 2) + ks * 32);
                uint32_t bb[2];
                ldsm_x2(bb, ba);
#pragma unroll
                for (int mi = 0; mi < 2; mi++)
                    mma_f16(acc[mi][ni], ah[mi], bb);
            }
        }
    }

    const int rbase = m0 + wm * 32 + (lane >> 2);
    const int cbase = wn * 32 + 2 * (lane & 3);
#pragma unroll
    for (int mi = 0; mi < 2; mi++) {
        int r0 = rbase + mi * 16;
        int r1 = r0 + 8;
#pragma unroll
        for (int ni = 0; ni < 4; ni++) {
            int col = cbase + ni * 8;
            if (r0 < NN)
                *(__half2*)(s1 + (size_t)r0 * NH + col) =
                    __floats2half2_rn(acc[mi][ni][0], acc[mi][ni][1]);
            if (r1 < NN)
                *(__half2*)(s1 + (size_t)r1 * NH + col) =
                    __floats2half2_rn(acc[mi][ni][2], acc[mi][ni][3]);
        }
    }
}

// ---------------- agg layer 1: 2 nodes/warp, uint4/lane, fp32 accum ----------
__global__ void k_agg1(const float* __restrict__ bias) {
    int gwarp = (blockIdx.x * blockDim.x + threadIdx.x) >> 5;
    int lane = threadIdx.x & 31;
    int grp = lane >> 4;                 // 0 or 1: which node in the warp
    int gl  = lane & 15;                 // lane within node group (8 feats each)
    int n = gwarp * 2 + grp;
    if (n >= NN) return;
    int cnt = g_cursor[n];
    if (cnt > CAP) cnt = CAP;
    const int2* ep = g_edge + n * CAP;   // 768B-aligned -> int4 pairs OK
    const char* s1b = (const char*)g_s1h;
    const uint32_t foff = (uint32_t)gl * 16;

    float acc[8];
#pragma unroll
    for (int q = 0; q < 8; q++) acc[q] = 0.f;

    int j = 0;
    for (; j + 2 <= cnt; j += 2) {
        int4 pp = *(const int4*)(ep + j);          // 2 edges
        float w0 = __int_as_float(pp.y), w1 = __int_as_float(pp.w);
        uint4 u0 = *(const uint4*)(s1b + (uint32_t)pp.x * 256u + foff);
        uint4 u1 = *(const uint4*)(s1b + (uint32_t)pp.z * 256u + foff);
        const __half2* h0 = (const __half2*)&u0;
        const __half2* h1 = (const __half2*)&u1;
#pragma unroll
        for (int q = 0; q < 4; q++) {
            float2 v0 = __half22float2(h0[q]);
            float2 v1 = __half22float2(h1[q]);
            acc[2 * q]     = fmaf(v0.x, w0, acc[2 * q]);
            acc[2 * q + 1] = fmaf(v0.y, w0, acc[2 * q + 1]);
            acc[2 * q]     = fmaf(v1.x, w1, acc[2 * q]);
            acc[2 * q + 1] = fmaf(v1.y, w1, acc[2 * q + 1]);
        }
    }
    if (j < cnt) {
        int2 e = ep[j];
        float w = __int_as_float(e.y);
        uint4 u = *(const uint4*)(s1b + (uint32_t)e.x * 256u + foff);
        const __half2* h = (const __half2*)&u;
#pragma unroll
        for (int q = 0; q < 4; q++) {
            float2 v = __half22float2(h[q]);
            acc[2 * q]     = fmaf(v.x, w, acc[2 * q]);
            acc[2 * q + 1] = fmaf(v.y, w, acc[2 * q + 1]);
        }
    }

    const float4* b4 = (const float4*)bias;
    float4 bv0 = b4[gl * 2], bv1 = b4[gl * 2 + 1];
    float bb[8] = {bv0.x, bv0.y, bv0.z, bv0.w, bv1.x, bv1.y, bv1.z, bv1.w};
    __half2 hh[4];
#pragma unroll
    for (int q = 0; q < 4; q++) {
        float a0 = fmaxf(acc[2 * q] + bb[2 * q], 0.f);
        float a1 = fmaxf(acc[2 * q + 1] + bb[2 * q + 1], 0.f);
        hh[q] = __floats2half2_rn(a0, a1);
    }
    *(uint4*)((char*)g_h + (size_t)n * 256 + foff) = *(uint4*)hh;
}

// ---------------- agg layer 2: fp16 gather + bias -> fp32 out ----------------
__global__ void k_agg2(const float* __restrict__ bias, float* __restrict__ out) {
    int idx = blockIdx.x * blockDim.x + threadIdx.x;
    int n = idx / 10;
    int f = idx % 10;
    if (n >= NN) return;
    int cnt = g_cursor[n];
    if (cnt > CAP) cnt = CAP;
    int beg = n * CAP, end = beg + cnt;
    const uint2* s2v = (const uint2*)g_s2h;
    float4 acc = make_float4(0.f, 0.f, 0.f, 0.f);
    int e = beg;
    for (; e + 1 < end; e += 2) {
        int2 e0 = g_edge[e], e1 = g_edge[e + 1];
        float w0 = __int_as_float(e0.y), w1 = __int_as_float(e1.y);
        uint2 u0 = s2v[(size_t)e0.x * 10 + f];
        uint2 u1 = s2v[(size_t)e1.x * 10 + f];
        float2 a0 = __half22float2(*(__half2*)&u0.x);
        float2 b0 = __half22float2(*(__half2*)&u0.y);
        float2 a1 = __half22float2(*(__half2*)&u1.x);
        float2 b1 = __half22float2(*(__half2*)&u1.y);
        acc.x = fmaf(a0.x, w0, acc.x); acc.y = fmaf(a0.y, w0, acc.y);
        acc.z = fmaf(b0.x, w0, acc.z); acc.w = fmaf(b0.y, w0, acc.w);
        acc.x = fmaf(a1.x, w1, acc.x); acc.y = fmaf(a1.y, w1, acc.y);
        acc.z = fmaf(b1.x, w1, acc.z); acc.w = fmaf(b1.y, w1, acc.w);
    }
    if (e < end) {
        int2 e0 = g_edge[e];
        float w = __int_as_float(e0.y);
        uint2 u = s2v[(size_t)e0.x * 10 + f];
        float2 a = __half22float2(*(__half2*)&u.x);
        float2 b = __half22float2(*(__half2*)&u.y);
        acc.x = fmaf(a.x, w, acc.x); acc.y = fmaf(a.y, w, acc.y);
        acc.z = fmaf(b.x, w, acc.z); acc.w = fmaf(b.y, w, acc.w);
    }
    float4 b = ((const float4*)bias)[f];
    acc.x += b.x; acc.y += b.y; acc.z += b.z; acc.w += b.w;
    ((float4*)out)[(size_t)n * 10 + f] = acc;
}

// ---------------- GEMM2: s2h = h @ W2 (A fp16, B split fp16 hi/lo; 2 MMA) ------
#define LDA2    136                        // fp16 per smem row (272 B)
#define APL     (128 * LDA2 * 2)           // 34816 B
#define BPL     (40 * LDA2 * 2)            // 10880 B
#define S2A     0
#define S2B_HI  APL
#define S2B_LO  (APL + BPL)
#define SMEM2_SZ (APL + 2 * BPL)           // 56576 B

__global__ __launch_bounds__(256) void k_gemm2_mma(__half* __restrict__ s2) {
    extern __shared__ __align__(16) char smem[];
    const uint32_t sb = smem_u32(smem);
    const int tid = threadIdx.x;
    const int lane = tid & 31;
    const int wid = tid >> 5;
    const int n0 = blockIdx.x * 128;

#pragma unroll
    for (int it = 0; it < 8; it++) {
        int idx = it * 256 + tid;
        int r = idx >> 4, g = idx & 15;
        int row = n0 + r;
        uint4 vh = make_uint4(0, 0, 0, 0);
        if (row < NN)
            vh = *(const uint4*)(g_h + (size_t)row * NH + g * 8);
        uint32_t off = (uint32_t)(r * (LDA2 * 2) + g * 16);
        asm volatile("st.shared.v4.b32 [%0], {%1,%2,%3,%4};"
                     :: "r"(sb + S2A + off), "r"(vh.x), "r"(vh.y), "r"(vh.z), "r"(vh.w));
    }
#pragma unroll
    for (int it = 0; it < 3; it++) {
        int idx = it * 256 + tid;
        if (idx < 640) {
            int r = idx >> 4, g = idx & 15;
            uint4 vh = *(const uint4*)(g_w2t_hi + (size_t)r * NH + g * 8);
            uint4 vl = *(const uint4*)(g_w2t_lo + (size_t)r * NH + g * 8);
            uint32_t off = (uint32_t)(r * (LDA2 * 2) + g * 16);
            asm volatile("st.shared.v4.b32 [%0], {%1,%2,%3,%4};"
                         :: "r"(sb + S2B_HI + off), "r"(vh.x), "r"(vh.y), "r"(vh.z), "r"(vh.w));
            asm volatile("st.shared.v4.b32 [%0], {%1,%2,%3,%4};"
                         :: "r"(sb + S2B_LO + off), "r"(vl.x), "r"(vl.y), "r"(vl.z), "r"(vl.w));
        }
    }
    __syncthreads();

    float acc[5][4];
#pragma unroll
    for (int i = 0; i < 5; i++)
#pragma unroll
        for (int q = 0; q < 4; q++) acc[i][q] = 0.f;

    const uint32_t a_base = sb + S2A +
        (uint32_t)(wid * 16 + (lane & 15)) * (LDA2 * 2) + (uint32_t)((lane >> 4) * 16);
    const uint32_t b_base = sb + S2B_HI +
        (uint32_t)(lane & 7) * (LDA2 * 2) + (uint32_t)(((lane >> 3) & 1) * 16);

#pragma unroll
    for (int ks = 0; ks < 8; ks++) {
        uint32_t ah[4];
        ldsm_x4(ah, a_base + (uint32_t)(ks * 32));
#pragma unroll
        for (int nt = 0; nt < 5; nt++) {
            uint32_t ba = b_base + (uint32_t)(nt * 8 * (LDA2 * 2) + ks * 32);
            uint32_t bh[2], bl[2];
            ldsm_x2(bh, ba);
            ldsm_x2(bl, ba + (uint32_t)(S2B_LO - S2B_HI));
            mma_f16(acc[nt], ah, bh);
            mma_f16(acc[nt], ah, bl);
        }
    }

    const int r0 = n0 + wid * 16 + (lane >> 2);
    const int r1 = r0 + 8;
    const int cb = 2 * (lane & 3);
#pragma unroll
    for (int nt = 0; nt < 5; nt++) {
        int col = cb + nt * 8;
        if (r0 < NN)
            *(__half2*)(s2 + (size_t)r0 * NC + col) =
                __floats2half2_rn(acc[nt][0], acc[nt][1]);
        if (r1 < NN)
            *(__half2*)(s2 + (size_t)r1 * NC + col) =
                __floats2half2_rn(acc[nt][2], acc[nt][3]);
    }
}

// ---------------- launcher with capture fork/join ----------------
extern "C" void kernel_launch(void* const* d_in, const int* in_sizes, int n_in,
                              void* d_out, int out_size) {
    const float* x  = (const float*)d_in[0];
    const int*   es = (const int*)d_in[1];
    const int*   ed = (const int*)d_in[2];
    const float* ew = (const float*)d_in[3];
    const float* W1 = (const float*)d_in[4];
    const float* b1 = (const float*)d_in[5];
    const float* W2 = (const float*)d_in[6];
    const float* b2 = (const float*)d_in[7];
    float* out = (float*)d_out;

    __half *s1p, *s2p;
    int *curp;
    cudaGetSymbolAddress((void**)&s1p, g_s1h);
    cudaGetSymbolAddress((void**)&s2p, g_s2h);
    cudaGetSymbolAddress((void**)&curp, g_cursor);

    cudaFuncSetAttribute(k_gemm1_mma, cudaFuncAttributeMaxDynamicSharedMemorySize, SMEM_SZ);
    cudaFuncSetAttribute(k_gemm2_mma, cudaFuncAttributeMaxDynamicSharedMemorySize, SMEM2_SZ);

    static cudaStream_t s2s = nullptr;
    static cudaEvent_t eFork = nullptr, eCSR = nullptr;
    if (!s2s) {
        cudaStreamCreateWithFlags(&s2s, cudaStreamNonBlocking);
        cudaEventCreateWithFlags(&eFork, cudaEventDisableTiming);
        cudaEventCreateWithFlags(&eCSR, cudaEventDisableTiming);
    }

    // fork: bucketed edge fill on side stream
    cudaEventRecord(eFork, 0);
    cudaStreamWaitEvent(s2s, eFork, 0);
    cudaMemsetAsync(curp, 0, NN * sizeof(int), s2s);
    k_fill4<<<(NE / 4 + 255) / 256, 256, 0, s2s>>>((const int4*)es, (const int4*)ed,
                                                   (const float4*)ew);
    cudaEventRecord(eCSR, s2s);

    // main stream: fused weight prep + GEMM1 (independent of edges)
    k_wsplit<<<(NF * NH + NH * NC + 255) / 256, 256>>>(W1, W2);
    k_gemm1_mma<<<(NN + BM - 1) / BM, 256, SMEM_SZ>>>(x, s1p);

    // join, then the dependent tail
    cudaStreamWaitEvent(0, eCSR, 0);
    // 2 nodes per warp: NN/2 warps
    k_agg1<<<((NN + 1) / 2 * 32 + 255) / 256, 256>>>(b1);
    k_gemm2_mma<<<(NN + 127) / 128, 256, SMEM2_SZ>>>(s2p);
    k_agg2<<<(NN * 10 + 255) / 256, 256>>>(b2, out);
}